// round 10
// baseline (speedup 1.0000x reference)
#include <cuda_runtime.h>
#include <stdint.h>

#define N1 12800          // 100*128 elements of tm1
#define N2 25600          // 100*256 elements of tm2
#define NT 38400
#define K1 6399           // (N1-1)//2 -> torch lower-median rank
#define K2 12799
#define NBLOCKS 148
#define EPB 260           // 148*260 = 38480 >= 38400
#define CCAP 4096         // compact buffer capacity per array

// -------- device scratch (reset by finisher every run) --------------------
__device__ unsigned int g_cnt[2][2048];       // level-1 count hists
__device__ uint2        g_compact[2][CCAP];   // median-bin {key,w} elements
__device__ unsigned int g_ccnt[2];            // compact counts
__device__ double       g_Ssuf[2];            // sum w over bins > d0
__device__ double       g_sum_p1, g_sum_p2;   // sum (t - vmask)^2
__device__ double       g_sum_a1, g_sum_a2;   // sum amask^2
__device__ unsigned int g_arrive1, g_arrive2;
__device__ unsigned int g_flag;
__device__ unsigned int g_d0[2], g_kin[2];

__device__ __forceinline__ unsigned int mono(unsigned int u) {
    return u ^ ((unsigned int)((int)u >> 31) | 0x80000000u);
}

// re-derive gathered value (fallback only)
__device__ __forceinline__ float regather(int a2, int idx,
                                          const float* c2, const float* c3)
{
    return a2 == 0 ? c2[(size_t)idx * 3136 + 399]
                   : c3[(size_t)idx * 784  + 87];
}

// ---------------------------------------------------------------------------
// Block-wide: find bin containing rank *k_sh in hist[0..nb); update *k_sh to
// rank-within-bin; return bin. blockDim.x == 1024, nb in {1024, 2048}.
// ---------------------------------------------------------------------------
__device__ unsigned int block_select(const unsigned int* hist, int nb,
                                     unsigned int* warpbuf,
                                     unsigned int* k_sh, unsigned int* sel_sh)
{
    int tid  = threadIdx.x;
    int lane = tid & 31;
    int warp = tid >> 5;
    int bpt  = nb >> 10;
    int base = tid * bpt;

    unsigned int local = 0;
    for (int j = 0; j < bpt; j++) local += hist[base + j];

    unsigned int incl = local;
    #pragma unroll
    for (int o = 1; o < 32; o <<= 1) {
        unsigned int t = __shfl_up_sync(0xffffffffu, incl, o);
        if (lane >= o) incl += t;
    }
    if (lane == 31) warpbuf[warp] = incl;
    __syncthreads();
    if (warp == 0) {
        unsigned int w = warpbuf[lane];
        unsigned int wi = w;
        #pragma unroll
        for (int o = 1; o < 32; o <<= 1) {
            unsigned int t = __shfl_up_sync(0xffffffffu, wi, o);
            if (lane >= o) wi += t;
        }
        warpbuf[lane] = wi - w;
    }
    __syncthreads();

    unsigned int ex = (incl - local) + warpbuf[warp];
    unsigned int k = *k_sh;
    __syncthreads();

    unsigned int c = ex;
    for (int j = 0; j < bpt; j++) {
        unsigned int h = hist[base + j];
        if (k >= c && k < c + h) {
            *sel_sh = (unsigned int)(base + j);
            *k_sh   = k - c;
        }
        c += h;
    }
    __syncthreads();
    return *sel_sh;
}

// block-wide float sum; all threads receive the result
__device__ float block_sum(float v, float* redf)
{
    int lane = threadIdx.x & 31;
    int warp = threadIdx.x >> 5;
    #pragma unroll
    for (int o = 16; o; o >>= 1) v += __shfl_down_sync(0xffffffffu, v, o);
    if (lane == 0) redf[warp] = v;
    __syncthreads();
    if (warp == 0) {
        float r = redf[lane];
        #pragma unroll
        for (int o = 16; o; o >>= 1) r += __shfl_down_sync(0xffffffffu, r, o);
        if (lane == 0) redf[0] = r;
    }
    __syncthreads();
    float r = redf[0];
    __syncthreads();
    return r;
}

// ---------------------------------------------------------------------------
__global__ void __launch_bounds__(1024) fused_kernel(
    const float* __restrict__ c2,  const float* __restrict__ c3,
    const float* __restrict__ vm1, const float* __restrict__ vm2,
    const float* __restrict__ am1, const float* __restrict__ am2,
    float* __restrict__ out)
{
    __shared__ unsigned int sh_cnt[2048];
    __shared__ unsigned int sk[CCAP];
    __shared__ float        sw[CCAP];
    __shared__ unsigned int warpbuf[32];
    __shared__ float        redf[32];
    __shared__ unsigned int k_sh, sel_sh, mkey_sh;
    __shared__ bool         is_lastA, is_lastB;

    int tid  = threadIdx.x;
    int lane = tid & 31;

    // ===================== round 1: gather + count hist =====================
    int e = blockIdx.x * EPB + tid;
    bool active = (tid < EPB) && (e < NT);
    unsigned int key = 0u, bin = 0u;
    float w = 0.f;
    int arr = 0;
    float p1 = 0.f, p2 = 0.f, a1s = 0.f, a2s = 0.f;

    if (active) {
        float t, v, a;
        if (e < N1) {
            t = c2[(size_t)e * 3136 + 399];          // [.,.,7,7]: 7*56+7
            v = vm1[e]; a = am1[e]; arr = 0;
        } else {
            int idx = e - N1;
            t = c3[(size_t)idx * 784 + 87];          // [.,.,3,3]: 3*28+3
            v = vm2[idx]; a = am2[idx]; arr = 1;
        }
        key = mono(__float_as_uint(t));
        w   = 1.0f - 2.0f * a;
        bin = key >> 21;
        atomicAdd(&g_cnt[arr][bin], 1u);             // the only gather atomic
        float d = t - v;
        if (arr == 0) { p1 = d * d; a1s = a * a; }
        else          { p2 = d * d; a2s = a * a; }
    }
    #pragma unroll
    for (int o = 16; o; o >>= 1) {
        p1  += __shfl_down_sync(0xffffffffu, p1,  o);
        p2  += __shfl_down_sync(0xffffffffu, p2,  o);
        a1s += __shfl_down_sync(0xffffffffu, a1s, o);
        a2s += __shfl_down_sync(0xffffffffu, a2s, o);
    }
    if (lane == 0) {
        if (p1  != 0.f) atomicAdd(&g_sum_p1, (double)p1);
        if (p2  != 0.f) atomicAdd(&g_sum_p2, (double)p2);
        if (a1s != 0.f) atomicAdd(&g_sum_a1, (double)a1s);
        if (a2s != 0.f) atomicAdd(&g_sum_a2, (double)a2s);
    }

    // ---- arrival 1
    __threadfence();
    __syncthreads();
    if (tid == 0)
        is_lastA = (atomicAdd(&g_arrive1, 1u) == (unsigned int)(NBLOCKS - 1));
    __syncthreads();

    // ---- last block: select d0 + rank-in-bin for both arrays, publish
    if (is_lastA) {
        for (int a2 = 0; a2 < 2; a2++) {
            for (int b = tid; b < 2048; b += 1024)
                sh_cnt[b] = __ldcg(&g_cnt[a2][b]);
            if (tid == 0) k_sh = a2 ? K2 : K1;
            __syncthreads();
            unsigned int d0 = block_select(sh_cnt, 2048, warpbuf, &k_sh, &sel_sh);
            if (tid == 0) { g_d0[a2] = d0; g_kin[a2] = k_sh; }
            __syncthreads();
        }
        if (tid == 0) { __threadfence(); atomicExch(&g_flag, 1u); }
    } else {
        if (tid == 0) {
            while (atomicAdd(&g_flag, 0u) == 0u) __nanosleep(64);
            __threadfence();
        }
    }
    __syncthreads();

    // ===================== round 2: suffix + compact (regs still live) ======
    float s1 = 0.f, s2 = 0.f;
    if (active) {
        unsigned int d0 = __ldcg(&g_d0[arr]);
        if (bin > d0) {
            if (arr == 0) s1 = w; else s2 = w;
        } else if (bin == d0) {
            unsigned int p = atomicAdd(&g_ccnt[arr], 1u);
            if (p < CCAP)
                g_compact[arr][p] = make_uint2(key, __float_as_uint(w));
        }
    }
    #pragma unroll
    for (int o = 16; o; o >>= 1) {
        s1 += __shfl_down_sync(0xffffffffu, s1, o);
        s2 += __shfl_down_sync(0xffffffffu, s2, o);
    }
    if (lane == 0) {
        if (s1 != 0.f) atomicAdd(&g_Ssuf[0], (double)s1);
        if (s2 != 0.f) atomicAdd(&g_Ssuf[1], (double)s2);
    }

    // ---- arrival 2
    __threadfence();
    __syncthreads();
    if (tid == 0)
        is_lastB = (atomicAdd(&g_arrive2, 1u) == (unsigned int)(NBLOCKS - 1));
    __syncthreads();
    if (!is_lastB) return;

    // ===================== finisher ==========================================
    double sp1 = __ldcg(&g_sum_p1);
    double sp2 = __ldcg(&g_sum_p2);
    double sa1 = __ldcg(&g_sum_a1);
    double sa2 = __ldcg(&g_sum_a2);
    double Ss0 = __ldcg(&g_Ssuf[0]);
    double Ss1 = __ldcg(&g_Ssuf[1]);

    float S[2];
    for (int a2 = 0; a2 < 2; a2++) {
        unsigned int nc  = __ldcg(&g_ccnt[a2]);
        unsigned int kin = __ldcg(&g_kin[a2]);
        unsigned int d0  = __ldcg(&g_d0[a2]);
        float s;

        if (nc <= CCAP) {
            // load compact set into shared (<=4 per thread)
            for (int j = tid; j < (int)nc; j += 1024) {
                uint2 kv = __ldcg(&g_compact[a2][j]);
                sk[j] = kv.x;
                sw[j] = __uint_as_float(kv.y);
            }
            __syncthreads();
            unsigned int mkey;
            if (nc <= 1024) {
                // count-select (expected nc ~ 10..60 for randn)
                if (tid < (int)nc) {
                    unsigned int mykey = sk[tid];
                    unsigned int less = 0, eq = 0;
                    for (unsigned int j = 0; j < nc; j++) {
                        unsigned int kj = sk[j];
                        less += (kj < mykey);
                        eq   += (kj == mykey);
                    }
                    if (less <= kin && kin < less + eq) mkey_sh = mykey;
                }
                __syncthreads();
                mkey = mkey_sh;
            } else {
                // radix select over the compact set (bits 20:10 then 9:0)
                if (tid == 0) k_sh = kin;
                for (int b = tid; b < 2048; b += 1024) sh_cnt[b] = 0u;
                __syncthreads();
                for (int j = tid; j < (int)nc; j += 1024)
                    atomicAdd(&sh_cnt[(sk[j] >> 10) & 2047u], 1u);
                __syncthreads();
                unsigned int d1 = block_select(sh_cnt, 2048, warpbuf, &k_sh, &sel_sh);
                sh_cnt[tid] = 0u;
                __syncthreads();
                for (int j = tid; j < (int)nc; j += 1024)
                    if (((sk[j] >> 10) & 2047u) == d1)
                        atomicAdd(&sh_cnt[sk[j] & 1023u], 1u);
                __syncthreads();
                unsigned int d2 = block_select(sh_cnt, 1024, warpbuf, &k_sh, &sel_sh);
                mkey = (d0 << 21) | (d1 << 10) | d2;
            }
            // within-bin suffix (ties included)
            float sl = 0.f;
            for (int j = tid; j < (int)nc; j += 1024)
                if (sk[j] >= mkey) sl += sw[j];
            s = block_sum(sl, redf);
        } else {
            // fallback: compact overflowed; recompute from inputs
            const float* am = a2 ? am2 : am1;
            int n = a2 ? N2 : N1;
            if (tid == 0) k_sh = kin;
            for (int b = tid; b < 2048; b += 1024) sh_cnt[b] = 0u;
            __syncthreads();
            for (int j = tid; j < n; j += 1024) {
                unsigned int kk = mono(__float_as_uint(regather(a2, j, c2, c3)));
                if ((kk >> 21) == d0) atomicAdd(&sh_cnt[(kk >> 10) & 2047u], 1u);
            }
            __syncthreads();
            unsigned int d1 = block_select(sh_cnt, 2048, warpbuf, &k_sh, &sel_sh);
            unsigned int p21 = (d0 << 11) | d1;
            sh_cnt[tid] = 0u;
            __syncthreads();
            for (int j = tid; j < n; j += 1024) {
                unsigned int kk = mono(__float_as_uint(regather(a2, j, c2, c3)));
                if ((kk >> 10) == p21) atomicAdd(&sh_cnt[kk & 1023u], 1u);
            }
            __syncthreads();
            unsigned int d2 = block_select(sh_cnt, 1024, warpbuf, &k_sh, &sel_sh);
            unsigned int mkey = (p21 << 10) | d2;
            float sl = 0.f;
            for (int j = tid; j < n; j += 1024) {
                unsigned int kk = mono(__float_as_uint(regather(a2, j, c2, c3)));
                if ((kk >> 21) == d0 && kk >= mkey) sl += 1.0f - 2.0f * am[j];
            }
            s = block_sum(sl, redf);
        }
        S[a2] = s;
        __syncthreads();          // shared reuse between the two arrays
    }

    // ===================== output + state reset =============================
    for (int b = tid; b < 2048; b += 1024) {
        g_cnt[0][b] = 0u;
        g_cnt[1][b] = 0u;
    }
    if (tid == 0) {
        double p = (sqrt(sp1) + sqrt(sp2)) * (1.0 / 38400.0);
        double q1sq = sa1 + Ss0 + (double)S[0];
        double q2sq = sa2 + Ss1 + (double)S[1];
        double q = (sqrt(q1sq) + sqrt(q2sq)) * (1.0 / 384.0);
        out[0] = (float)p;
        out[1] = (float)q;
        g_sum_p1 = 0.0; g_sum_p2 = 0.0;
        g_sum_a1 = 0.0; g_sum_a2 = 0.0;
        g_Ssuf[0] = 0.0; g_Ssuf[1] = 0.0;
        g_ccnt[0] = 0u; g_ccnt[1] = 0u;
        g_arrive1 = 0u; g_arrive2 = 0u;
        g_flag = 0u;
    }
}

// ---------------------------------------------------------------------------
extern "C" void kernel_launch(void* const* d_in, const int* in_sizes, int n_in,
                              void* d_out, int out_size)
{
    const float* c2  = (const float*)d_in[0];
    const float* c3  = (const float*)d_in[1];
    const float* vm1 = (const float*)d_in[2];
    const float* vm2 = (const float*)d_in[3];
    const float* am1 = (const float*)d_in[4];
    const float* am2 = (const float*)d_in[5];
    float* out = (float*)d_out;

    fused_kernel<<<NBLOCKS, 1024>>>(c2, c3, vm1, vm2, am1, am2, out);
}

// round 11
// speedup vs baseline: 1.2416x; 1.2416x over previous
#include <cuda_runtime.h>
#include <stdint.h>

#define N1 12800          // 100*128 elements of tm1
#define N2 25600          // 100*256 elements of tm2
#define NT 38400
#define K1 6399           // (N1-1)//2 -> torch lower-median rank
#define K2 12799
#define NBLOCKS 148
#define EPB 260           // 148*260 = 38480 >= 38400
#define CAP 2048          // per-bin bucket capacity
#define SMALL 512         // small-set selection threshold

// 64-bit fused histogram cell: [63:40] count, [39:0] sum of (w*4096 + 65536)
#define HIST_ONE   (1ULL << 40)
#define HIST_MASK  ((1ULL << 40) - 1ULL)
#define W_SCALE    4096.0f
#define W_BIAS     65536LL

// -------- device scratch (reset in-kernel every run) ----------------------
__device__ unsigned long long g_hist[2][2048];    // fused cnt+weight hists
__device__ uint2              g_bkt[2 * 2048 * CAP]; // packed {key, w} buckets
__device__ double             g_sum_p1, g_sum_p2; // sum (t - vmask)^2
__device__ double             g_sum_a1, g_sum_a2; // sum amask^2
__device__ unsigned int       g_arrive;

__device__ __forceinline__ unsigned int mono(unsigned int u) {
    return u ^ ((unsigned int)((int)u >> 31) | 0x80000000u);
}

// re-derive gathered value (fallback only)
__device__ __forceinline__ float regather(int a2, int idx,
                                          const float* c2, const float* c3)
{
    return a2 == 0 ? c2[(size_t)idx * 3136 + 399]
                   : c3[(size_t)idx * 784  + 87];
}

// ---------------------------------------------------------------------------
// Block-wide: find bin containing rank *k_sh in hist[0..nb); update *k_sh to
// rank-within-bin; return bin. blockDim.x == 1024, nb in {1024, 2048}.
// ---------------------------------------------------------------------------
__device__ unsigned int block_select(const unsigned int* hist, int nb,
                                     unsigned int* warpbuf,
                                     unsigned int* k_sh, unsigned int* sel_sh)
{
    int tid  = threadIdx.x;
    int lane = tid & 31;
    int warp = tid >> 5;
    int bpt  = nb >> 10;
    int base = tid * bpt;

    unsigned int local = 0;
    for (int j = 0; j < bpt; j++) local += hist[base + j];

    unsigned int incl = local;
    #pragma unroll
    for (int o = 1; o < 32; o <<= 1) {
        unsigned int t = __shfl_up_sync(0xffffffffu, incl, o);
        if (lane >= o) incl += t;
    }
    if (lane == 31) warpbuf[warp] = incl;
    __syncthreads();
    if (warp == 0) {
        unsigned int w = warpbuf[lane];
        unsigned int wi = w;
        #pragma unroll
        for (int o = 1; o < 32; o <<= 1) {
            unsigned int t = __shfl_up_sync(0xffffffffu, wi, o);
            if (lane >= o) wi += t;
        }
        warpbuf[lane] = wi - w;
    }
    __syncthreads();

    unsigned int ex = (incl - local) + warpbuf[warp];
    unsigned int k = *k_sh;
    __syncthreads();

    unsigned int c = ex;
    for (int j = 0; j < bpt; j++) {
        unsigned int h = hist[base + j];
        if (k >= c && k < c + h) {
            *sel_sh = (unsigned int)(base + j);
            *k_sh   = k - c;
        }
        c += h;
    }
    __syncthreads();
    return *sel_sh;
}

// block-wide float sum; all threads receive the result
__device__ float block_sum(float v, float* redf)
{
    int lane = threadIdx.x & 31;
    int warp = threadIdx.x >> 5;
    #pragma unroll
    for (int o = 16; o; o >>= 1) v += __shfl_down_sync(0xffffffffu, v, o);
    if (lane == 0) redf[warp] = v;
    __syncthreads();
    if (warp == 0) {
        float r = redf[lane];
        #pragma unroll
        for (int o = 16; o; o >>= 1) r += __shfl_down_sync(0xffffffffu, r, o);
        if (lane == 0) redf[0] = r;
    }
    __syncthreads();
    float r = redf[0];
    __syncthreads();
    return r;
}

// ---------------------------------------------------------------------------
__global__ void __launch_bounds__(1024) fused_kernel(
    const float* __restrict__ c2,  const float* __restrict__ c3,
    const float* __restrict__ vm1, const float* __restrict__ vm2,
    const float* __restrict__ am1, const float* __restrict__ am2,
    float* __restrict__ out)
{
    __shared__ unsigned int sh_cnt[2048];
    __shared__ float        sh_w[2048];
    __shared__ unsigned int sk[SMALL];
    __shared__ float        sw[SMALL];
    __shared__ unsigned int warpbuf[32];
    __shared__ float        redf[32];
    __shared__ unsigned int k_sh, sel_sh, mkey_sh;
    __shared__ bool         is_last;

    int tid  = threadIdx.x;
    int lane = tid & 31;

    // ===================== gather (all blocks, EPB elems each) ==============
    float p1 = 0.f, p2 = 0.f, a1s = 0.f, a2s = 0.f;
    int e = blockIdx.x * EPB + tid;
    if (tid < EPB && e < NT) {
        float t, v, a;
        int arr;
        if (e < N1) {
            t = c2[(size_t)e * 3136 + 399];         // [.,.,7,7]: 7*56+7
            v = vm1[e]; a = am1[e]; arr = 0;
        } else {
            int idx = e - N1;
            t = c3[(size_t)idx * 784 + 87];         // [.,.,3,3]: 3*28+3
            v = vm2[idx]; a = am2[idx]; arr = 1;
        }
        unsigned int key = mono(__float_as_uint(t));
        float w = 1.0f - 2.0f * a;
        unsigned int bin = key >> 21;

        // ---- single fused atomic: count + biased fixed-point weight
        long long wfix = (long long)rintf(w * W_SCALE);   // |w|<16 -> |wfix|<65536
        unsigned long long add = HIST_ONE + (unsigned long long)(wfix + W_BIAS);
        unsigned long long old = atomicAdd(&g_hist[arr][bin], add);
        unsigned int pos = (unsigned int)(old >> 40);
        if (pos < CAP) {
            size_t slot = (size_t)(((unsigned)arr << 11) | bin) * CAP + pos;
            g_bkt[slot] = make_uint2(key, __float_as_uint(w));
        }
        float d = t - v;
        if (arr == 0) { p1 = d * d; a1s = a * a; }
        else          { p2 = d * d; a2s = a * a; }
    }
    #pragma unroll
    for (int o = 16; o; o >>= 1) {
        p1  += __shfl_down_sync(0xffffffffu, p1,  o);
        p2  += __shfl_down_sync(0xffffffffu, p2,  o);
        a1s += __shfl_down_sync(0xffffffffu, a1s, o);
        a2s += __shfl_down_sync(0xffffffffu, a2s, o);
    }
    if (lane == 0) {
        if (p1  != 0.f) atomicAdd(&g_sum_p1, (double)p1);
        if (p2  != 0.f) atomicAdd(&g_sum_p2, (double)p2);
        if (a1s != 0.f) atomicAdd(&g_sum_a1, (double)a1s);
        if (a2s != 0.f) atomicAdd(&g_sum_a2, (double)a2s);
    }

    // ===================== grid arrival =====================================
    __threadfence();
    __syncthreads();
    if (tid == 0) {
        unsigned int r = atomicAdd(&g_arrive, 1u);
        is_last = (r == (unsigned int)(gridDim.x - 1));
    }
    __syncthreads();
    if (!is_last) return;

    // ===================== finalize (last block only) =======================
    double sp1 = __ldcg(&g_sum_p1);
    double sp2 = __ldcg(&g_sum_p2);
    double sa1 = __ldcg(&g_sum_a1);
    double sa2 = __ldcg(&g_sum_a2);

    float S[2];
    const unsigned int kranks[2] = {K1, K2};

    for (int arr = 0; arr < 2; arr++) {
        // ---- one trip: fused hist -> decoded cnt + weight in shared
        for (int b = tid; b < 2048; b += 1024) {
            unsigned long long v = __ldcg(&g_hist[arr][b]);
            unsigned int cnt = (unsigned int)(v >> 40);
            long long    lw  = (long long)(v & HIST_MASK)
                             - (long long)cnt * W_BIAS;
            sh_cnt[b] = cnt;
            sh_w[b]   = (float)lw * (1.0f / W_SCALE);
        }
        if (tid == 0) k_sh = kranks[arr];
        __syncthreads();

        // ---- level 1: select bin holding the median rank
        unsigned int d0 = block_select(sh_cnt, 2048, warpbuf, &k_sh, &sel_sh);

        // suffix weight over bins strictly above d0
        float s1 = 0.f;
        for (int b = tid; b < 2048; b += 1024)
            if (b > (int)d0) s1 += sh_w[b];
        float Sx = block_sum(s1, redf);

        unsigned int nc = sh_cnt[d0];
        unsigned int k  = k_sh;                 // rank within bin
        __syncthreads();
        size_t slotbase = (size_t)(((unsigned)arr << 11) | d0) * CAP;

        if (nc <= SMALL) {
            // ======= small-set path (expected: nc ~ 1..60 for randn) ========
            if (tid < (int)nc) {
                uint2 kv = __ldcg(&g_bkt[slotbase + tid]);
                sk[tid] = kv.x;
                sw[tid] = __uint_as_float(kv.y);
            }
            __syncthreads();
            if (tid < (int)nc) {
                unsigned int key = sk[tid];
                unsigned int less = 0, eq = 0;
                for (unsigned int j = 0; j < nc; j++) {
                    unsigned int kj = sk[j];
                    less += (kj < key);
                    eq   += (kj == key);
                }
                if (less <= k && k < less + eq) mkey_sh = key;
            }
            __syncthreads();
            unsigned int mkey = mkey_sh;
            float s = (tid < (int)nc && sk[tid] >= mkey) ? sw[tid] : 0.f;
            Sx += block_sum(s, redf);
        } else if (nc <= CAP) {
            // ======= histogram path over the bucket =======
            unsigned int key0 = 0u, key1 = 0u;
            float        w0 = 0.f, w1 = 0.f;
            bool h0 = (tid < (int)nc), h1 = (tid + 1024 < (int)nc);
            if (h0) { uint2 kv = __ldcg(&g_bkt[slotbase + tid]);
                      key0 = kv.x; w0 = __uint_as_float(kv.y); }
            if (h1) { uint2 kv = __ldcg(&g_bkt[slotbase + tid + 1024]);
                      key1 = kv.x; w1 = __uint_as_float(kv.y); }
            // level 2: bits [20:10]
            for (int b = tid; b < 2048; b += 1024) sh_cnt[b] = 0u;
            __syncthreads();
            if (h0) atomicAdd(&sh_cnt[(key0 >> 10) & 2047u], 1u);
            if (h1) atomicAdd(&sh_cnt[(key1 >> 10) & 2047u], 1u);
            __syncthreads();
            unsigned int d1 = block_select(sh_cnt, 2048, warpbuf, &k_sh, &sel_sh);
            // level 3: bits [9:0]
            sh_cnt[tid] = 0u;
            __syncthreads();
            if (h0 && ((key0 >> 10) & 2047u) == d1) atomicAdd(&sh_cnt[key0 & 1023u], 1u);
            if (h1 && ((key1 >> 10) & 2047u) == d1) atomicAdd(&sh_cnt[key1 & 1023u], 1u);
            __syncthreads();
            unsigned int d2 = block_select(sh_cnt, 1024, warpbuf, &k_sh, &sel_sh);
            unsigned int mkey = (d0 << 21) | (d1 << 10) | d2;
            float s = 0.f;
            if (h0 && key0 >= mkey) s += w0;
            if (h1 && key1 >= mkey) s += w1;
            Sx += block_sum(s, redf);
        } else {
            // ======= fallback: bucket overflowed, recompute from inputs =====
            const float* am = arr ? am2 : am1;
            int n = arr ? N2 : N1;
            for (int b = tid; b < 2048; b += 1024) sh_cnt[b] = 0u;
            __syncthreads();
            for (int j = tid; j < n; j += 1024) {
                unsigned int key = mono(__float_as_uint(regather(arr, j, c2, c3)));
                if ((key >> 21) == d0) atomicAdd(&sh_cnt[(key >> 10) & 2047u], 1u);
            }
            __syncthreads();
            unsigned int d1 = block_select(sh_cnt, 2048, warpbuf, &k_sh, &sel_sh);
            unsigned int p21 = (d0 << 11) | d1;
            sh_cnt[tid] = 0u;
            __syncthreads();
            for (int j = tid; j < n; j += 1024) {
                unsigned int key = mono(__float_as_uint(regather(arr, j, c2, c3)));
                if ((key >> 10) == p21) atomicAdd(&sh_cnt[key & 1023u], 1u);
            }
            __syncthreads();
            unsigned int d2 = block_select(sh_cnt, 1024, warpbuf, &k_sh, &sel_sh);
            unsigned int mkey = (p21 << 10) | d2;
            float s = 0.f;
            for (int j = tid; j < n; j += 1024) {
                unsigned int key = mono(__float_as_uint(regather(arr, j, c2, c3)));
                if ((key >> 21) == d0 && key >= mkey) s += 1.0f - 2.0f * am[j];
            }
            Sx += block_sum(s, redf);
        }
        S[arr] = Sx;
    }

    // ===================== output + state reset =============================
    __syncthreads();
    for (int b = tid; b < 2048; b += 1024) {
        g_hist[0][b] = 0ULL;
        g_hist[1][b] = 0ULL;
    }
    if (tid == 0) {
        double p = (sqrt(sp1) + sqrt(sp2)) * (1.0 / 38400.0);
        double q1sq = sa1 + (double)S[0];
        double q2sq = sa2 + (double)S[1];
        double q = (sqrt(q1sq) + sqrt(q2sq)) * (1.0 / 384.0);
        out[0] = (float)p;
        out[1] = (float)q;
        g_sum_p1 = 0.0; g_sum_p2 = 0.0;
        g_sum_a1 = 0.0; g_sum_a2 = 0.0;
        g_arrive = 0u;
    }
}

// ---------------------------------------------------------------------------
extern "C" void kernel_launch(void* const* d_in, const int* in_sizes, int n_in,
                              void* d_out, int out_size)
{
    const float* c2  = (const float*)d_in[0];
    const float* c3  = (const float*)d_in[1];
    const float* vm1 = (const float*)d_in[2];
    const float* vm2 = (const float*)d_in[3];
    const float* am1 = (const float*)d_in[4];
    const float* am2 = (const float*)d_in[5];
    float* out = (float*)d_out;

    fused_kernel<<<NBLOCKS, 1024>>>(c2, c3, vm1, vm2, am1, am2, out);
}

// round 12
// speedup vs baseline: 1.2940x; 1.0423x over previous
#include <cuda_runtime.h>
#include <stdint.h>

#define N1 12800          // 100*128 elements of tm1
#define N2 25600          // 100*256 elements of tm2
#define NT 38400
#define K1 6399           // (N1-1)//2 -> torch lower-median rank
#define K2 12799
#define NBLOCKS 148
#define EPB 260           // 148*260 = 38480 >= 38400
#define CAP 2048          // per-bin bucket capacity
#define SMALL 512         // small-set selection threshold

// 64-bit fused histogram cell: [63:40] count, [39:0] sum of (w*4096 + 65536)
#define HIST_ONE   (1ULL << 40)
#define HIST_MASK  ((1ULL << 40) - 1ULL)
#define W_SCALE    4096.0f
#define W_BIAS     65536LL

// -------- device scratch (reset in-kernel every run) ----------------------
__device__ unsigned long long g_hist[2][2048];       // fused cnt+weight hists
__device__ uint2              g_bkt[2 * 2048 * CAP]; // packed {key, w} buckets
__device__ double             g_sum_p1, g_sum_p2;    // sum (t - vmask)^2
__device__ double             g_sum_a1, g_sum_a2;    // sum amask^2
__device__ unsigned int       g_arrive;

__device__ __forceinline__ unsigned int mono(unsigned int u) {
    return u ^ ((unsigned int)((int)u >> 31) | 0x80000000u);
}

// re-derive gathered value (fallback only)
__device__ __forceinline__ float regather(int a2, int idx,
                                          const float* c2, const float* c3)
{
    return a2 == 0 ? c2[(size_t)idx * 3136 + 399]
                   : c3[(size_t)idx * 784  + 87];
}

// ------------------- fallback-only helpers (block-wide) -------------------
__device__ unsigned int block_select(const unsigned int* hist, int nb,
                                     unsigned int* warpbuf,
                                     unsigned int* k_sh, unsigned int* sel_sh)
{
    int tid  = threadIdx.x;
    int lane = tid & 31;
    int warp = tid >> 5;
    int bpt  = nb >> 10;
    int base = tid * bpt;

    unsigned int local = 0;
    for (int j = 0; j < bpt; j++) local += hist[base + j];

    unsigned int incl = local;
    #pragma unroll
    for (int o = 1; o < 32; o <<= 1) {
        unsigned int t = __shfl_up_sync(0xffffffffu, incl, o);
        if (lane >= o) incl += t;
    }
    if (lane == 31) warpbuf[warp] = incl;
    __syncthreads();
    if (warp == 0) {
        unsigned int w = warpbuf[lane];
        unsigned int wi = w;
        #pragma unroll
        for (int o = 1; o < 32; o <<= 1) {
            unsigned int t = __shfl_up_sync(0xffffffffu, wi, o);
            if (lane >= o) wi += t;
        }
        warpbuf[lane] = wi - w;
    }
    __syncthreads();

    unsigned int ex = (incl - local) + warpbuf[warp];
    unsigned int k = *k_sh;
    __syncthreads();

    unsigned int c = ex;
    for (int j = 0; j < bpt; j++) {
        unsigned int h = hist[base + j];
        if (k >= c && k < c + h) {
            *sel_sh = (unsigned int)(base + j);
            *k_sh   = k - c;
        }
        c += h;
    }
    __syncthreads();
    return *sel_sh;
}

__device__ float block_sum(float v, float* redf)
{
    int lane = threadIdx.x & 31;
    int warp = threadIdx.x >> 5;
    #pragma unroll
    for (int o = 16; o; o >>= 1) v += __shfl_down_sync(0xffffffffu, v, o);
    if (lane == 0) redf[warp] = v;
    __syncthreads();
    if (warp == 0) {
        float r = redf[lane];
        #pragma unroll
        for (int o = 16; o; o >>= 1) r += __shfl_down_sync(0xffffffffu, r, o);
        if (lane == 0) redf[0] = r;
    }
    __syncthreads();
    float r = redf[0];
    __syncthreads();
    return r;
}

// ---------------------------------------------------------------------------
__global__ void __launch_bounds__(1024) fused_kernel(
    const float* __restrict__ c2,  const float* __restrict__ c3,
    const float* __restrict__ vm1, const float* __restrict__ vm2,
    const float* __restrict__ am1, const float* __restrict__ am2,
    float* __restrict__ out)
{
    __shared__ unsigned int wt_c[2][16];
    __shared__ float        wt_w[2][16];
    __shared__ unsigned int d0_sh[2], kin_sh[2], nc_sh[2], ovf_sh[2];
    __shared__ float        suf_sh[2];
    __shared__ unsigned int sk[2][SMALL];
    __shared__ float        sw[2][SMALL];
    __shared__ unsigned int mkey_sh[2];
    __shared__ float        S_sh[2];
    __shared__ unsigned int fb_hist[2048];
    __shared__ unsigned int warpbuf[32];
    __shared__ float        redf[32];
    __shared__ unsigned int k_sh, sel_sh;
    __shared__ bool         is_last;

    int tid  = threadIdx.x;
    int lane = tid & 31;

    // ===================== gather (identical to R10 winner) =================
    float p1 = 0.f, p2 = 0.f, a1s = 0.f, a2s = 0.f;
    int e = blockIdx.x * EPB + tid;
    if (tid < EPB && e < NT) {
        float t, v, a;
        int arr;
        if (e < N1) {
            t = c2[(size_t)e * 3136 + 399];         // [.,.,7,7]: 7*56+7
            v = vm1[e]; a = am1[e]; arr = 0;
        } else {
            int idx = e - N1;
            t = c3[(size_t)idx * 784 + 87];         // [.,.,3,3]: 3*28+3
            v = vm2[idx]; a = am2[idx]; arr = 1;
        }
        unsigned int key = mono(__float_as_uint(t));
        float w = 1.0f - 2.0f * a;
        unsigned int bin = key >> 21;

        long long wfix = (long long)rintf(w * W_SCALE);
        unsigned long long add = HIST_ONE + (unsigned long long)(wfix + W_BIAS);
        unsigned long long old = atomicAdd(&g_hist[arr][bin], add);
        unsigned int pos = (unsigned int)(old >> 40);
        if (pos < CAP) {
            size_t slot = (size_t)(((unsigned)arr << 11) | bin) * CAP + pos;
            g_bkt[slot] = make_uint2(key, __float_as_uint(w));
        }
        float d = t - v;
        if (arr == 0) { p1 = d * d; a1s = a * a; }
        else          { p2 = d * d; a2s = a * a; }
    }
    #pragma unroll
    for (int o = 16; o; o >>= 1) {
        p1  += __shfl_down_sync(0xffffffffu, p1,  o);
        p2  += __shfl_down_sync(0xffffffffu, p2,  o);
        a1s += __shfl_down_sync(0xffffffffu, a1s, o);
        a2s += __shfl_down_sync(0xffffffffu, a2s, o);
    }
    if (lane == 0) {
        if (p1  != 0.f) atomicAdd(&g_sum_p1, (double)p1);
        if (p2  != 0.f) atomicAdd(&g_sum_p2, (double)p2);
        if (a1s != 0.f) atomicAdd(&g_sum_a1, (double)a1s);
        if (a2s != 0.f) atomicAdd(&g_sum_a2, (double)a2s);
    }

    // ===================== grid arrival =====================================
    __threadfence();
    __syncthreads();
    if (tid == 0) {
        unsigned int r = atomicAdd(&g_arrive, 1u);
        is_last = (r == (unsigned int)(gridDim.x - 1));
    }
    __syncthreads();
    if (!is_last) return;

    // ===================== finalize: both arrays concurrent =================
    double sp1 = __ldcg(&g_sum_p1);
    double sp2 = __ldcg(&g_sum_p2);
    double sa1 = __ldcg(&g_sum_a1);
    double sa2 = __ldcg(&g_sum_a2);

    int half    = tid >> 9;          // 0/1 == array index
    int htid    = tid & 511;
    int hwarp   = htid >> 5;         // 0..15
    int arr     = half;
    int binbase = htid << 2;         // 4 bins per thread

    // ---- trip 1: load fused hist, decode cnt + weight into registers
    unsigned int cnt[4];
    float        wsm[4];
    #pragma unroll
    for (int j = 0; j < 4; j++) {
        unsigned long long v = __ldcg(&g_hist[arr][binbase + j]);
        unsigned int c = (unsigned int)(v >> 40);
        long long    lw = (long long)(v & HIST_MASK) - (long long)c * W_BIAS;
        cnt[j] = c;
        wsm[j] = (float)lw * (1.0f / W_SCALE);
    }
    // reset hist now (fire-and-forget; values live in registers)
    #pragma unroll
    for (int j = 0; j < 4; j++) g_hist[arr][binbase + j] = 0ULL;

    // ---- fused level-1 select + suffix-weight (2 barriers)
    unsigned int lc = cnt[0] + cnt[1] + cnt[2] + cnt[3];
    float        lw = wsm[0] + wsm[1] + wsm[2] + wsm[3];
    unsigned int ic = lc; float iw = lw;
    #pragma unroll
    for (int o = 1; o < 32; o <<= 1) {
        unsigned int tc = __shfl_up_sync(0xffffffffu, ic, o);
        float        tw = __shfl_up_sync(0xffffffffu, iw, o);
        if (lane >= o) { ic += tc; iw += tw; }
    }
    if (lane == 31) { wt_c[half][hwarp] = ic; wt_w[half][hwarp] = iw; }
    __syncthreads();

    unsigned int woff_c = 0; float woff_w = 0.f, total_w = 0.f;
    #pragma unroll
    for (int w2 = 0; w2 < 16; w2++) {
        unsigned int cc = wt_c[half][w2];
        float        ww = wt_w[half][w2];
        if (w2 < hwarp) { woff_c += cc; woff_w += ww; }
        total_w += ww;
    }
    unsigned int ex  = woff_c + (ic - lc);
    float        exw = woff_w + (iw - lw);
    unsigned int K   = arr ? K2 : K1;
    {
        unsigned int c = ex; float wp = exw;
        #pragma unroll
        for (int j = 0; j < 4; j++) {
            if (K >= c && K < c + cnt[j]) {
                d0_sh[half]  = (unsigned int)(binbase + j);
                kin_sh[half] = K - c;
                suf_sh[half] = total_w - (wp + wsm[j]);
                nc_sh[half]  = cnt[j];
                ovf_sh[half] = (cnt[j] > SMALL) ? 1u : 0u;
            }
            c += cnt[j]; wp += wsm[j];
        }
    }
    __syncthreads();

    if (!(ovf_sh[0] | ovf_sh[1])) {
        // =============== fast path: small-set median, halves concurrent ====
        unsigned int d0  = d0_sh[half];
        unsigned int kin = kin_sh[half];
        unsigned int nc  = nc_sh[half];
        size_t slotbase = (size_t)(((unsigned)arr << 11) | d0) * CAP;

        // trip 2: bucket data (one element per thread; nc <= 512)
        if (htid < (int)nc) {
            uint2 kv = __ldcg(&g_bkt[slotbase + htid]);
            sk[half][htid] = kv.x;
            sw[half][htid] = __uint_as_float(kv.y);
        }
        __syncthreads();
        if (htid < (int)nc) {
            unsigned int mykey = sk[half][htid];
            unsigned int less = 0, eq = 0;
            for (unsigned int j = 0; j < nc; j++) {
                unsigned int kj = sk[half][j];
                less += (kj < mykey);
                eq   += (kj == mykey);
            }
            if (less <= kin && kin < less + eq) mkey_sh[half] = mykey;
        }
        __syncthreads();
        unsigned int mkey = mkey_sh[half];
        float s = (htid < (int)nc && sk[half][htid] >= mkey) ? sw[half][htid] : 0.f;
        #pragma unroll
        for (int o = 16; o; o >>= 1) s += __shfl_down_sync(0xffffffffu, s, o);
        if (lane == 0) wt_w[half][hwarp] = s;
        __syncthreads();
        if (htid == 0) {
            float tsum = 0.f;
            #pragma unroll
            for (int j = 0; j < 16; j++) tsum += wt_w[half][j];
            S_sh[half] = suf_sh[half] + tsum;
        }
    } else {
        // =============== fallback: recompute from inputs (block-wide) ======
        __syncthreads();
        for (int a2 = 0; a2 < 2; a2++) {
            unsigned int fd0 = d0_sh[a2];
            int n = a2 ? N2 : N1;
            const float* am = a2 ? am2 : am1;
            if (tid == 0) k_sh = kin_sh[a2];
            for (int b = tid; b < 2048; b += 1024) fb_hist[b] = 0u;
            __syncthreads();
            for (int j = tid; j < n; j += 1024) {
                unsigned int kk = mono(__float_as_uint(regather(a2, j, c2, c3)));
                if ((kk >> 21) == fd0) atomicAdd(&fb_hist[(kk >> 10) & 2047u], 1u);
            }
            __syncthreads();
            unsigned int d1 = block_select(fb_hist, 2048, warpbuf, &k_sh, &sel_sh);
            unsigned int p21 = (fd0 << 11) | d1;
            fb_hist[tid] = 0u;
            __syncthreads();
            for (int j = tid; j < n; j += 1024) {
                unsigned int kk = mono(__float_as_uint(regather(a2, j, c2, c3)));
                if ((kk >> 10) == p21) atomicAdd(&fb_hist[kk & 1023u], 1u);
            }
            __syncthreads();
            unsigned int d2 = block_select(fb_hist, 1024, warpbuf, &k_sh, &sel_sh);
            unsigned int mkey = (p21 << 10) | d2;
            float s = 0.f;
            for (int j = tid; j < n; j += 1024) {
                unsigned int kk = mono(__float_as_uint(regather(a2, j, c2, c3)));
                if ((kk >> 21) == fd0 && kk >= mkey) s += 1.0f - 2.0f * am[j];
            }
            s = block_sum(s, redf);
            if (tid == 0) S_sh[a2] = suf_sh[a2] + s;
            __syncthreads();
        }
    }
    __syncthreads();

    // ===================== output + remaining state reset ===================
    if (tid == 0) {
        double p = (sqrt(sp1) + sqrt(sp2)) * (1.0 / 38400.0);
        double q1sq = sa1 + (double)S_sh[0];
        double q2sq = sa2 + (double)S_sh[1];
        double q = (sqrt(q1sq) + sqrt(q2sq)) * (1.0 / 384.0);
        out[0] = (float)p;
        out[1] = (float)q;
        g_sum_p1 = 0.0; g_sum_p2 = 0.0;
        g_sum_a1 = 0.0; g_sum_a2 = 0.0;
        g_arrive = 0u;
    }
}

// ---------------------------------------------------------------------------
extern "C" void kernel_launch(void* const* d_in, const int* in_sizes, int n_in,
                              void* d_out, int out_size)
{
    const float* c2  = (const float*)d_in[0];
    const float* c3  = (const float*)d_in[1];
    const float* vm1 = (const float*)d_in[2];
    const float* vm2 = (const float*)d_in[3];
    const float* am1 = (const float*)d_in[4];
    const float* am2 = (const float*)d_in[5];
    float* out = (float*)d_out;

    fused_kernel<<<NBLOCKS, 1024>>>(c2, c3, vm1, vm2, am1, am2, out);
}